// round 6
// baseline (speedup 1.0000x reference)
#include <cuda_runtime.h>
#include <cuda_fp16.h>
#include <math.h>
#include <stdint.h>

// ---------------------------------------------------------------------------
// E64AdditiveHCell — fp16 mma.sync + ldmatrix edition
//  1) prepass: convert X, Wa, Wx to fp16 (rn)
//  2) dual fp16 tensor-core GEMM (m16n8k16, fp32 accum), 4-stage cp.async,
//     ldmatrix fragment loads:
//     alpha = sigmoid(X Wa^T + ba), wx = X Wx^T + b  -> interleaved float2
//  3) recurrence over T (tanh.approx) with fused out = h^2 * sigmoid(h)
// ---------------------------------------------------------------------------

#define BM 128
#define BN 128
#define NKS 32                 // K stages: 1024 / 32
#define NSTG 4
#define HST_B 80               // smem row stride in bytes (40 halves)
#define A_BYTES (128 * HST_B)  // 10240
#define STG_BYTES (3 * A_BYTES)
#define A_OFF  0
#define BA_OFF A_BYTES
#define BW_OFF (2 * A_BYTES)

#define MAX_T 2048
#define MAX_BD 8192
#define MAX_M 16384
#define MAX_K 1024
__device__ float2 g_aw[(size_t)MAX_T * MAX_BD];     // {alpha, wx}
__device__ __half g_x [(size_t)MAX_M * MAX_K];
__device__ __half g_wa[(size_t)MAX_K * MAX_K];
__device__ __half g_wx[(size_t)MAX_K * MAX_K];

// ---------------- helpers ----------------
__device__ __forceinline__ float ex2f(float x) {
    float r; asm("ex2.approx.ftz.f32 %0, %1;" : "=f"(r) : "f"(x)); return r;
}
__device__ __forceinline__ float rcpf(float x) {
    float r; asm("rcp.approx.ftz.f32 %0, %1;" : "=f"(r) : "f"(x)); return r;
}
__device__ __forceinline__ float tanhx(float x) {
    float r; asm("tanh.approx.f32 %0, %1;" : "=f"(r) : "f"(x)); return r;
}
__device__ __forceinline__ float fast_sigmoid(float x) {
    return rcpf(1.0f + ex2f(-1.4426950408889634f * x));
}
__device__ __forceinline__ void mma_f16(float c[4], const uint32_t a[4],
                                        uint32_t b0, uint32_t b1) {
    asm volatile(
        "mma.sync.aligned.m16n8k16.row.col.f32.f16.f16.f32 "
        "{%0,%1,%2,%3},{%4,%5,%6,%7},{%8,%9},{%0,%1,%2,%3};"
        : "+f"(c[0]), "+f"(c[1]), "+f"(c[2]), "+f"(c[3])
        : "r"(a[0]), "r"(a[1]), "r"(a[2]), "r"(a[3]), "r"(b0), "r"(b1));
}
__device__ __forceinline__ void ldsm4(uint32_t r[4], uint32_t addr) {
    asm volatile("ldmatrix.sync.aligned.m8n8.x4.shared.b16 {%0,%1,%2,%3}, [%4];"
        : "=r"(r[0]), "=r"(r[1]), "=r"(r[2]), "=r"(r[3]) : "r"(addr));
}
__device__ __forceinline__ void cp16(uint32_t dst, const void* src) {
    asm volatile("cp.async.cg.shared.global [%0], [%1], 16;" :: "r"(dst), "l"(src));
}
__device__ __forceinline__ void cp_commit() { asm volatile("cp.async.commit_group;"); }
__device__ __forceinline__ void cp_wait0()  { asm volatile("cp.async.wait_group 0;" ::: "memory"); }
__device__ __forceinline__ void cp_wait1()  { asm volatile("cp.async.wait_group 1;" ::: "memory"); }
__device__ __forceinline__ void cp_wait2()  { asm volatile("cp.async.wait_group 2;" ::: "memory"); }

// ---------------------------------------------------------------------------
// 1) fp32 -> fp16 prepass
// ---------------------------------------------------------------------------
__global__ void __launch_bounds__(256)
f2h_kernel(const float* __restrict__ src, __half* __restrict__ dst, int n4)
{
    int i = blockIdx.x * blockDim.x + threadIdx.x;
    if (i >= n4) return;
    float4 v = ((const float4*)src)[i];
    __half2 h0 = __floats2half2_rn(v.x, v.y);
    __half2 h1 = __floats2half2_rn(v.z, v.w);
    uint2 o;
    o.x = *(uint32_t*)&h0;
    o.y = *(uint32_t*)&h1;
    ((uint2*)dst)[i] = o;
}

// ---------------------------------------------------------------------------
// 2) fused dual fp16 GEMM: 256 threads, warps 2(m) x 4(n), warp tile 64x32/W
//    ldmatrix fragment loads.
// ---------------------------------------------------------------------------
extern __shared__ __align__(128) char smem_raw[];

__global__ void __launch_bounds__(256, 1)
gemm2_f16(const __half* __restrict__ X,  const __half* __restrict__ Wa,
          const __half* __restrict__ Wx, const float* __restrict__ ba,
          const float* __restrict__ bb)
{
    __shared__ float s_ba[BN], s_bb[BN];

    const int t    = threadIdx.x;
    const int lane = t & 31;
    const int warp = t >> 5;
    const int g    = lane >> 2;
    const int tid4 = lane & 3;
    const int wm   = warp >> 2;
    const int wn   = warp & 3;
    const int m0   = blockIdx.y * BM;
    const int n0   = blockIdx.x * BN;

    uint32_t dyn_u32 = (uint32_t)__cvta_generic_to_shared(smem_raw);

    if (t < BN) { s_ba[t] = ba[n0 + t]; s_bb[t] = bb[n0 + t]; }

    float accA[4][4][4];
    float accW[4][4][4];
#pragma unroll
    for (int mi = 0; mi < 4; mi++)
#pragma unroll
        for (int ni = 0; ni < 4; ni++)
#pragma unroll
            for (int r = 0; r < 4; r++) { accA[mi][ni][r] = 0.f; accW[mi][ni][r] = 0.f; }

    // ---- per-lane ldmatrix base offsets (within a stage) ----
    // A fragment (m16k16): lane -> row m + (lane&15), 16B-col (lane>>4)
    uint32_t aBase[4];
#pragma unroll
    for (int mi = 0; mi < 4; mi++) {
        int row = wm * 64 + mi * 16 + (lane & 15);
        aBase[mi] = dyn_u32 + A_OFF + (uint32_t)(row * HST_B) + ((lane >> 4) << 4);
    }
    // B fragments, ni pairs p={0,1}: matrices [ni.b0, ni.b1, ni1.b0, ni1.b1]
    // lane -> row nbase + ((lane>>4)<<3) + (lane&7), 16B-col (lane>>3)&1
    uint32_t bBaseA[2], bBaseW[2];
#pragma unroll
    for (int p = 0; p < 2; p++) {
        int row = wn * 32 + p * 16 + ((lane >> 4) << 3) + (lane & 7);
        uint32_t off = (uint32_t)(row * HST_B) + (((lane >> 3) & 1) << 4);
        bBaseA[p] = dyn_u32 + BA_OFF + off;
        bBaseW[p] = dyn_u32 + BW_OFF + off;
    }

    const __half* Xb  = X  + (size_t)m0 * MAX_K;
    const __half* Wab = Wa + (size_t)n0 * MAX_K;
    const __half* Wxb = Wx + (size_t)n0 * MAX_K;

    auto issue = [&](int ks, int b) {
        uint32_t dbase = dyn_u32 + (uint32_t)b * STG_BYTES;
        const size_t kof = (size_t)ks * 32;    // halves
#pragma unroll
        for (int i = 0; i < 2; i++) {
            int ch  = i * 256 + t;             // 512 chunks of 16B per matrix
            int row = ch >> 2, q = ch & 3;
            uint32_t so = (uint32_t)(row * HST_B + q * 16);
            size_t go = (size_t)row * MAX_K + kof + (size_t)q * 8;
            cp16(dbase + A_OFF  + so, Xb  + go);
            cp16(dbase + BA_OFF + so, Wab + go);
            cp16(dbase + BW_OFF + so, Wxb + go);
        }
        cp_commit();
    };

    issue(0, 0); issue(1, 1); issue(2, 2);

    for (int c = 0; c < NKS; c++) {
        const uint32_t stgofs = (uint32_t)(c & 3) * STG_BYTES;
        if (c < NKS - 2)       cp_wait2();
        else if (c == NKS - 2) cp_wait1();
        else                   cp_wait0();
        __syncthreads();
        if (c + 3 < NKS) issue(c + 3, (c + 3) & 3);

#pragma unroll
        for (int kk = 0; kk < 2; kk++) {
            const uint32_t kb = stgofs + kk * 32;
            uint32_t af[4][4];
#pragma unroll
            for (int mi = 0; mi < 4; mi++) ldsm4(af[mi], aBase[mi] + kb);
            uint32_t bfA[2][4], bfW[2][4];
#pragma unroll
            for (int p = 0; p < 2; p++) {
                ldsm4(bfA[p], bBaseA[p] + kb);
                ldsm4(bfW[p], bBaseW[p] + kb);
            }
#pragma unroll
            for (int mi = 0; mi < 4; mi++)
#pragma unroll
                for (int ni = 0; ni < 4; ni++) {
                    const int p = ni >> 1, s = (ni & 1) * 2;
                    mma_f16(accA[mi][ni], af[mi], bfA[p][s], bfA[p][s + 1]);
                    mma_f16(accW[mi][ni], af[mi], bfW[p][s], bfW[p][s + 1]);
                }
        }
    }
    __syncthreads();

    // Epilogue: bias + fast sigmoid(alpha), interleaved float2 scratch
#pragma unroll
    for (int ni = 0; ni < 4; ni++) {
        const int col0 = n0 + wn * 32 + ni * 8 + 2 * tid4;
        const float ba0 = s_ba[col0 - n0], ba1 = s_ba[col0 - n0 + 1];
        const float bb0 = s_bb[col0 - n0], bb1 = s_bb[col0 - n0 + 1];
#pragma unroll
        for (int mi = 0; mi < 4; mi++) {
            const int row0 = m0 + wm * 64 + mi * 16 + g;
            {
                float4 v;
                v.x = fast_sigmoid(accA[mi][ni][0] + ba0);
                v.y = accW[mi][ni][0] + bb0;
                v.z = fast_sigmoid(accA[mi][ni][1] + ba1);
                v.w = accW[mi][ni][1] + bb1;
                *(float4*)&g_aw[(size_t)row0 * MAX_K + col0] = v;
            }
            {
                float4 v;
                v.x = fast_sigmoid(accA[mi][ni][2] + ba0);
                v.y = accW[mi][ni][2] + bb0;
                v.z = fast_sigmoid(accA[mi][ni][3] + ba1);
                v.w = accW[mi][ni][3] + bb1;
                *(float4*)&g_aw[(size_t)(row0 + 8) * MAX_K + col0] = v;
            }
        }
    }
}

// ---------------------------------------------------------------------------
// 3) Recurrence with fused out: out = h^2 * sigmoid(h) (silu off the chain)
// ---------------------------------------------------------------------------
__global__ void __launch_bounds__(32)
recur_kernel(const float* __restrict__ h0,
             float* __restrict__ out,   // [T, BD]
             float* __restrict__ hout,  // [T+1, BD]
             int T, int BD)
{
    const int idx = blockIdx.x * blockDim.x + threadIdx.x;
    if (idx >= BD) return;

    float h = h0[idx];
    hout[idx] = h;

    const float2* __restrict__ aw = g_aw + idx;
    float* __restrict__ hw = hout + BD + idx;
    float* __restrict__ ow = out + idx;

    float2 buf0[16], buf1[16];
#pragma unroll
    for (int u = 0; u < 16; u++) buf0[u] = aw[(size_t)u * BD];

    for (int tt = 0; tt < T; tt += 32) {
#pragma unroll
        for (int u = 0; u < 16; u++) buf1[u] = aw[(size_t)(tt + 16 + u) * BD];
#pragma unroll
        for (int u = 0; u < 16; u++) {
            const float a = buf0[u].x, w = buf0[u].y;
            float v = tanhx(h + w);
            h = fmaf(a, h - v, v);
            float sg = fast_sigmoid(h);
            size_t o = (size_t)(tt + u) * BD;
            ow[o] = h * h * sg;
            hw[o] = h;
        }
        if (tt + 32 < T) {
#pragma unroll
            for (int u = 0; u < 16; u++) buf0[u] = aw[(size_t)(tt + 32 + u) * BD];
        }
#pragma unroll
        for (int u = 0; u < 16; u++) {
            const float a = buf1[u].x, w = buf1[u].y;
            float v = tanhx(h + w);
            h = fmaf(a, h - v, v);
            float sg = fast_sigmoid(h);
            size_t o = (size_t)(tt + 16 + u) * BD;
            ow[o] = h * h * sg;
            hw[o] = h;
        }
    }
}

// ---------------------------------------------------------------------------
extern "C" void kernel_launch(void* const* d_in, const int* in_sizes, int n_in,
                              void* d_out, int out_size)
{
    const float* x  = (const float*)d_in[0];
    const float* h0 = (const float*)d_in[1];
    const float* Wa = (const float*)d_in[2];
    const float* ba = (const float*)d_in[3];
    const float* Wx = (const float*)d_in[4];
    const float* bb = (const float*)d_in[5];

    const int BD = in_sizes[1];               // 8192
    const int D  = in_sizes[3];               // 1024
    const int M  = in_sizes[0] / D;           // 16384
    const int T  = in_sizes[0] / BD;          // 2048

    float* out  = (float*)d_out;
    float* hout = (float*)d_out + (size_t)T * BD;

    __half* gx;  cudaGetSymbolAddress((void**)&gx,  g_x);
    __half* gwa; cudaGetSymbolAddress((void**)&gwa, g_wa);
    __half* gwx; cudaGetSymbolAddress((void**)&gwx, g_wx);

    // 1) fp16 prepass
    {
        int nx4 = (M * D) / 4;
        int nw4 = (D * D) / 4;
        f2h_kernel<<<(nx4 + 255) / 256, 256>>>(x,  gx,  nx4);
        f2h_kernel<<<(nw4 + 255) / 256, 256>>>(Wa, gwa, nw4);
        f2h_kernel<<<(nw4 + 255) / 256, 256>>>(Wx, gwx, nw4);
    }

    // 2) dual fp16 GEMM
    const int SMEM_BYTES = NSTG * STG_BYTES;        // 122880
    cudaFuncSetAttribute(gemm2_f16, cudaFuncAttributeMaxDynamicSharedMemorySize, SMEM_BYTES);
    dim3 grid(D / BN, M / BM);   // (8, 128) = 1024 CTAs
    gemm2_f16<<<grid, 256, SMEM_BYTES>>>(gx, gwa, gwx, ba, bb);

    // 3) recurrence + fused out
    recur_kernel<<<(BD + 31) / 32, 32>>>(h0, out, hout, T, BD);
}

// round 7
// speedup vs baseline: 1.0728x; 1.0728x over previous
#include <cuda_runtime.h>
#include <cuda_fp16.h>
#include <math.h>
#include <stdint.h>

// ---------------------------------------------------------------------------
// E64AdditiveHCell — fp16 mma.sync + ldmatrix, BK=64 edition
//  1) prepass: convert X, Wa, Wx to fp16 (rn)
//  2) dual fp16 tensor-core GEMM (m16n8k16, fp32 accum), 3-stage cp.async,
//     BK=64 (16 chunks -> half the sync bubbles), ldmatrix fragment loads:
//     alpha = sigmoid(X Wa^T + ba), wx = X Wx^T + b  -> interleaved float2
//  3) recurrence over T (tanh.approx, h only)
//  4) out = h^2 * sigmoid(h) (separate bandwidth kernel)
// ---------------------------------------------------------------------------

#define BM 128
#define BN 128
#define NKS 16                 // K chunks: 1024 / 64
#define HST_B 144              // smem row stride in bytes (64 halves + 16B pad)
#define A_BYTES (128 * HST_B)  // 18432
#define STG_BYTES (3 * A_BYTES)
#define A_OFF  0
#define BA_OFF A_BYTES
#define BW_OFF (2 * A_BYTES)

#define MAX_T 2048
#define MAX_BD 8192
#define MAX_M 16384
#define MAX_K 1024
__device__ float2 g_aw[(size_t)MAX_T * MAX_BD];     // {alpha, wx}
__device__ __half g_x [(size_t)MAX_M * MAX_K];
__device__ __half g_wa[(size_t)MAX_K * MAX_K];
__device__ __half g_wx[(size_t)MAX_K * MAX_K];

// ---------------- helpers ----------------
__device__ __forceinline__ float ex2f(float x) {
    float r; asm("ex2.approx.ftz.f32 %0, %1;" : "=f"(r) : "f"(x)); return r;
}
__device__ __forceinline__ float rcpf(float x) {
    float r; asm("rcp.approx.ftz.f32 %0, %1;" : "=f"(r) : "f"(x)); return r;
}
__device__ __forceinline__ float tanhx(float x) {
    float r; asm("tanh.approx.f32 %0, %1;" : "=f"(r) : "f"(x)); return r;
}
__device__ __forceinline__ float fast_sigmoid(float x) {
    return rcpf(1.0f + ex2f(-1.4426950408889634f * x));
}
__device__ __forceinline__ void mma_f16(float c[4], const uint32_t a[4],
                                        uint32_t b0, uint32_t b1) {
    asm volatile(
        "mma.sync.aligned.m16n8k16.row.col.f32.f16.f16.f32 "
        "{%0,%1,%2,%3},{%4,%5,%6,%7},{%8,%9},{%0,%1,%2,%3};"
        : "+f"(c[0]), "+f"(c[1]), "+f"(c[2]), "+f"(c[3])
        : "r"(a[0]), "r"(a[1]), "r"(a[2]), "r"(a[3]), "r"(b0), "r"(b1));
}
__device__ __forceinline__ void ldsm4(uint32_t r[4], uint32_t addr) {
    asm volatile("ldmatrix.sync.aligned.m8n8.x4.shared.b16 {%0,%1,%2,%3}, [%4];"
        : "=r"(r[0]), "=r"(r[1]), "=r"(r[2]), "=r"(r[3]) : "r"(addr));
}
__device__ __forceinline__ void cp16(uint32_t dst, const void* src) {
    asm volatile("cp.async.cg.shared.global [%0], [%1], 16;" :: "r"(dst), "l"(src));
}
__device__ __forceinline__ void cp_commit() { asm volatile("cp.async.commit_group;"); }
__device__ __forceinline__ void cp_wait0()  { asm volatile("cp.async.wait_group 0;" ::: "memory"); }
__device__ __forceinline__ void cp_wait1()  { asm volatile("cp.async.wait_group 1;" ::: "memory"); }

// ---------------------------------------------------------------------------
// 1) fp32 -> fp16 prepass
// ---------------------------------------------------------------------------
__global__ void __launch_bounds__(256)
f2h_kernel(const float* __restrict__ src, __half* __restrict__ dst, int n4)
{
    int i = blockIdx.x * blockDim.x + threadIdx.x;
    if (i >= n4) return;
    float4 v = ((const float4*)src)[i];
    __half2 h0 = __floats2half2_rn(v.x, v.y);
    __half2 h1 = __floats2half2_rn(v.z, v.w);
    uint2 o;
    o.x = *(uint32_t*)&h0;
    o.y = *(uint32_t*)&h1;
    ((uint2*)dst)[i] = o;
}

// ---------------------------------------------------------------------------
// 2) fused dual fp16 GEMM: 256 threads, warps 2(m) x 4(n), warp tile 64x32/W
// ---------------------------------------------------------------------------
extern __shared__ __align__(128) char smem_raw[];

__global__ void __launch_bounds__(256, 1)
gemm2_f16(const __half* __restrict__ X,  const __half* __restrict__ Wa,
          const __half* __restrict__ Wx, const float* __restrict__ ba,
          const float* __restrict__ bb)
{
    __shared__ float s_ba[BN], s_bb[BN];

    const int t    = threadIdx.x;
    const int lane = t & 31;
    const int warp = t >> 5;
    const int g    = lane >> 2;
    const int tid4 = lane & 3;
    const int wm   = warp >> 2;
    const int wn   = warp & 3;
    const int m0   = blockIdx.y * BM;
    const int n0   = blockIdx.x * BN;

    uint32_t dyn_u32 = (uint32_t)__cvta_generic_to_shared(smem_raw);

    if (t < BN) { s_ba[t] = ba[n0 + t]; s_bb[t] = bb[n0 + t]; }

    float accA[4][4][4];
    float accW[4][4][4];
#pragma unroll
    for (int mi = 0; mi < 4; mi++)
#pragma unroll
        for (int ni = 0; ni < 4; ni++)
#pragma unroll
            for (int r = 0; r < 4; r++) { accA[mi][ni][r] = 0.f; accW[mi][ni][r] = 0.f; }

    // ---- per-lane ldmatrix base offsets (within a stage) ----
    uint32_t aBase[4];
#pragma unroll
    for (int mi = 0; mi < 4; mi++) {
        int row = wm * 64 + mi * 16 + (lane & 15);
        aBase[mi] = dyn_u32 + A_OFF + (uint32_t)(row * HST_B) + ((lane >> 4) << 4);
    }
    uint32_t bBaseA[2], bBaseW[2];
#pragma unroll
    for (int p = 0; p < 2; p++) {
        int row = wn * 32 + p * 16 + ((lane >> 4) << 3) + (lane & 7);
        uint32_t off = (uint32_t)(row * HST_B) + (((lane >> 3) & 1) << 4);
        bBaseA[p] = dyn_u32 + BA_OFF + off;
        bBaseW[p] = dyn_u32 + BW_OFF + off;
    }

    const __half* Xb  = X  + (size_t)m0 * MAX_K;
    const __half* Wab = Wa + (size_t)n0 * MAX_K;
    const __half* Wxb = Wx + (size_t)n0 * MAX_K;

    // stage staging: 1024 16B-chunks per matrix per chunk (128 rows x 8)
    auto issue = [&](int ks, int b) {
        uint32_t dbase = dyn_u32 + (uint32_t)b * STG_BYTES;
        const size_t kof = (size_t)ks * 64;    // halves
#pragma unroll
        for (int i = 0; i < 4; i++) {
            int ch  = i * 256 + t;
            int row = ch >> 3, q = ch & 7;
            uint32_t so = (uint32_t)(row * HST_B + q * 16);
            size_t go = (size_t)row * MAX_K + kof + (size_t)q * 8;
            cp16(dbase + A_OFF  + so, Xb  + go);
            cp16(dbase + BA_OFF + so, Wab + go);
            cp16(dbase + BW_OFF + so, Wxb + go);
        }
        cp_commit();
    };

    issue(0, 0); issue(1, 1);

    for (int c = 0; c < NKS; c++) {
        const uint32_t stgofs = (uint32_t)(c % 3) * STG_BYTES;
        if (c < NKS - 1) cp_wait1(); else cp_wait0();
        __syncthreads();
        if (c + 2 < NKS) issue(c + 2, (c + 2) % 3);

#pragma unroll
        for (int kk = 0; kk < 4; kk++) {
            const uint32_t kb = stgofs + kk * 32;
            uint32_t af[4][4];
#pragma unroll
            for (int mi = 0; mi < 4; mi++) ldsm4(af[mi], aBase[mi] + kb);
            uint32_t bfA[2][4], bfW[2][4];
#pragma unroll
            for (int p = 0; p < 2; p++) {
                ldsm4(bfA[p], bBaseA[p] + kb);
                ldsm4(bfW[p], bBaseW[p] + kb);
            }
#pragma unroll
            for (int mi = 0; mi < 4; mi++)
#pragma unroll
                for (int ni = 0; ni < 4; ni++) {
                    const int p = ni >> 1, s = (ni & 1) * 2;
                    mma_f16(accA[mi][ni], af[mi], bfA[p][s], bfA[p][s + 1]);
                    mma_f16(accW[mi][ni], af[mi], bfW[p][s], bfW[p][s + 1]);
                }
        }
    }
    __syncthreads();

    // Epilogue: bias + fast sigmoid(alpha), interleaved float2 scratch
#pragma unroll
    for (int ni = 0; ni < 4; ni++) {
        const int col0 = n0 + wn * 32 + ni * 8 + 2 * tid4;
        const float ba0 = s_ba[col0 - n0], ba1 = s_ba[col0 - n0 + 1];
        const float bb0 = s_bb[col0 - n0], bb1 = s_bb[col0 - n0 + 1];
#pragma unroll
        for (int mi = 0; mi < 4; mi++) {
            const int row0 = m0 + wm * 64 + mi * 16 + g;
            {
                float4 v;
                v.x = fast_sigmoid(accA[mi][ni][0] + ba0);
                v.y = accW[mi][ni][0] + bb0;
                v.z = fast_sigmoid(accA[mi][ni][1] + ba1);
                v.w = accW[mi][ni][1] + bb1;
                *(float4*)&g_aw[(size_t)row0 * MAX_K + col0] = v;
            }
            {
                float4 v;
                v.x = fast_sigmoid(accA[mi][ni][2] + ba0);
                v.y = accW[mi][ni][2] + bb0;
                v.z = fast_sigmoid(accA[mi][ni][3] + ba1);
                v.w = accW[mi][ni][3] + bb1;
                *(float4*)&g_aw[(size_t)(row0 + 8) * MAX_K + col0] = v;
            }
        }
    }
}

// ---------------------------------------------------------------------------
// 3) Recurrence: tanh.approx, h only, 2-deep prefetch
// ---------------------------------------------------------------------------
__global__ void __launch_bounds__(64)
recur_kernel(const float* __restrict__ h0,
             float* __restrict__ hout,  // [T+1, BD]
             int T, int BD)
{
    const int idx = blockIdx.x * blockDim.x + threadIdx.x;
    if (idx >= BD) return;

    float h = h0[idx];
    hout[idx] = h;

    const float2* __restrict__ aw = g_aw + idx;
    float* __restrict__ hw = hout + BD + idx;

    float2 buf0[16], buf1[16];
#pragma unroll
    for (int u = 0; u < 16; u++) buf0[u] = aw[(size_t)u * BD];

    for (int tt = 0; tt < T; tt += 32) {
#pragma unroll
        for (int u = 0; u < 16; u++) buf1[u] = aw[(size_t)(tt + 16 + u) * BD];
#pragma unroll
        for (int u = 0; u < 16; u++) {
            const float a = buf0[u].x, w = buf0[u].y;
            float v = tanhx(h + w);
            h = fmaf(a, h - v, v);
            hw[(size_t)(tt + u) * BD] = h;
        }
        if (tt + 32 < T) {
#pragma unroll
            for (int u = 0; u < 16; u++) buf0[u] = aw[(size_t)(tt + 32 + u) * BD];
        }
#pragma unroll
        for (int u = 0; u < 16; u++) {
            const float a = buf1[u].x, w = buf1[u].y;
            float v = tanhx(h + w);
            h = fmaf(a, h - v, v);
            hw[(size_t)(tt + 16 + u) * BD] = h;
        }
    }
}

// ---------------------------------------------------------------------------
// 4) out = h^2 * sigmoid(h)
// ---------------------------------------------------------------------------
__global__ void __launch_bounds__(256)
out_kernel(const float* __restrict__ hsrc, float* __restrict__ out, int n4)
{
    int i = blockIdx.x * blockDim.x + threadIdx.x;
    if (i >= n4) return;
    float4 v = ((const float4*)hsrc)[i];
    float4 o;
    o.x = v.x * v.x * fast_sigmoid(v.x);
    o.y = v.y * v.y * fast_sigmoid(v.y);
    o.z = v.z * v.z * fast_sigmoid(v.z);
    o.w = v.w * v.w * fast_sigmoid(v.w);
    ((float4*)out)[i] = o;
}

// ---------------------------------------------------------------------------
extern "C" void kernel_launch(void* const* d_in, const int* in_sizes, int n_in,
                              void* d_out, int out_size)
{
    const float* x  = (const float*)d_in[0];
    const float* h0 = (const float*)d_in[1];
    const float* Wa = (const float*)d_in[2];
    const float* ba = (const float*)d_in[3];
    const float* Wx = (const float*)d_in[4];
    const float* bb = (const float*)d_in[5];

    const int BD = in_sizes[1];               // 8192
    const int D  = in_sizes[3];               // 1024
    const int M  = in_sizes[0] / D;           // 16384
    const int T  = in_sizes[0] / BD;          // 2048

    float* out  = (float*)d_out;
    float* hout = (float*)d_out + (size_t)T * BD;

    __half* gx;  cudaGetSymbolAddress((void**)&gx,  g_x);
    __half* gwa; cudaGetSymbolAddress((void**)&gwa, g_wa);
    __half* gwx; cudaGetSymbolAddress((void**)&gwx, g_wx);

    // 1) fp16 prepass
    {
        int nx4 = (M * D) / 4;
        int nw4 = (D * D) / 4;
        f2h_kernel<<<(nx4 + 255) / 256, 256>>>(x,  gx,  nx4);
        f2h_kernel<<<(nw4 + 255) / 256, 256>>>(Wa, gwa, nw4);
        f2h_kernel<<<(nw4 + 255) / 256, 256>>>(Wx, gwx, nw4);
    }

    // 2) dual fp16 GEMM
    const int SMEM_BYTES = 3 * STG_BYTES;           // 165888
    cudaFuncSetAttribute(gemm2_f16, cudaFuncAttributeMaxDynamicSharedMemorySize, SMEM_BYTES);
    dim3 grid(D / BN, M / BM);   // (8, 128) = 1024 CTAs
    gemm2_f16<<<grid, 256, SMEM_BYTES>>>(gx, gwa, gwx, ba, bb);

    // 3) recurrence (h only)
    recur_kernel<<<(BD + 63) / 64, 64>>>(h0, hout, T, BD);

    // 4) out = h * silu(h)
    int no4 = (T * BD) / 4;
    out_kernel<<<(no4 + 255) / 256, 256>>>(hout + BD, out, no4);
}

// round 8
// speedup vs baseline: 1.1597x; 1.0810x over previous
#include <cuda_runtime.h>
#include <cuda_fp16.h>
#include <math.h>
#include <stdint.h>

// ---------------------------------------------------------------------------
// E64AdditiveHCell — fp16 mma.sync + ldmatrix, BK=64, 16-warp edition
//  1) prepass: convert X, Wa, Wx to fp16 (rn)
//  2) dual fp16 tensor-core GEMM (m16n8k16, fp32 accum), 3-stage cp.async,
//     512 threads (4 warps/SMSP for latency hiding), warp tile 32x32 per W:
//     alpha = sigmoid(X Wa^T + ba), wx = X Wx^T + b  -> interleaved float2
//  3) recurrence over T (tanh.approx, h only, 32-step prefetch groups)
//  4) out = h^2 * sigmoid(h)
// ---------------------------------------------------------------------------

#define BM 128
#define BN 128
#define NKS 16                 // K chunks: 1024 / 64
#define HST_B 144              // smem row stride in bytes (64 halves + 16B pad)
#define A_BYTES (128 * HST_B)  // 18432
#define STG_BYTES (3 * A_BYTES)
#define A_OFF  0
#define BA_OFF A_BYTES
#define BW_OFF (2 * A_BYTES)

#define MAX_T 2048
#define MAX_BD 8192
#define MAX_M 16384
#define MAX_K 1024
__device__ float2 g_aw[(size_t)MAX_T * MAX_BD];     // {alpha, wx}
__device__ __half g_x [(size_t)MAX_M * MAX_K];
__device__ __half g_wa[(size_t)MAX_K * MAX_K];
__device__ __half g_wx[(size_t)MAX_K * MAX_K];

// ---------------- helpers ----------------
__device__ __forceinline__ float ex2f(float x) {
    float r; asm("ex2.approx.ftz.f32 %0, %1;" : "=f"(r) : "f"(x)); return r;
}
__device__ __forceinline__ float rcpf(float x) {
    float r; asm("rcp.approx.ftz.f32 %0, %1;" : "=f"(r) : "f"(x)); return r;
}
__device__ __forceinline__ float tanhx(float x) {
    float r; asm("tanh.approx.f32 %0, %1;" : "=f"(r) : "f"(x)); return r;
}
__device__ __forceinline__ float fast_sigmoid(float x) {
    return rcpf(1.0f + ex2f(-1.4426950408889634f * x));
}
__device__ __forceinline__ void mma_f16(float c[4], const uint32_t a[4],
                                        uint32_t b0, uint32_t b1) {
    asm volatile(
        "mma.sync.aligned.m16n8k16.row.col.f32.f16.f16.f32 "
        "{%0,%1,%2,%3},{%4,%5,%6,%7},{%8,%9},{%0,%1,%2,%3};"
        : "+f"(c[0]), "+f"(c[1]), "+f"(c[2]), "+f"(c[3])
        : "r"(a[0]), "r"(a[1]), "r"(a[2]), "r"(a[3]), "r"(b0), "r"(b1));
}
__device__ __forceinline__ void ldsm4(uint32_t r[4], uint32_t addr) {
    asm volatile("ldmatrix.sync.aligned.m8n8.x4.shared.b16 {%0,%1,%2,%3}, [%4];"
        : "=r"(r[0]), "=r"(r[1]), "=r"(r[2]), "=r"(r[3]) : "r"(addr));
}
__device__ __forceinline__ void cp16(uint32_t dst, const void* src) {
    asm volatile("cp.async.cg.shared.global [%0], [%1], 16;" :: "r"(dst), "l"(src));
}
__device__ __forceinline__ void cp_commit() { asm volatile("cp.async.commit_group;"); }
__device__ __forceinline__ void cp_wait0()  { asm volatile("cp.async.wait_group 0;" ::: "memory"); }
__device__ __forceinline__ void cp_wait1()  { asm volatile("cp.async.wait_group 1;" ::: "memory"); }

// ---------------------------------------------------------------------------
// 1) fp32 -> fp16 prepass
// ---------------------------------------------------------------------------
__global__ void __launch_bounds__(256)
f2h_kernel(const float* __restrict__ src, __half* __restrict__ dst, int n4)
{
    int i = blockIdx.x * blockDim.x + threadIdx.x;
    if (i >= n4) return;
    float4 v = ((const float4*)src)[i];
    __half2 h0 = __floats2half2_rn(v.x, v.y);
    __half2 h1 = __floats2half2_rn(v.z, v.w);
    uint2 o;
    o.x = *(uint32_t*)&h0;
    o.y = *(uint32_t*)&h1;
    ((uint2*)dst)[i] = o;
}

// ---------------------------------------------------------------------------
// 2) fused dual fp16 GEMM: 512 threads, warps 4(m) x 4(n), warp tile 32x32/W
// ---------------------------------------------------------------------------
extern __shared__ __align__(128) char smem_raw[];

__global__ void __launch_bounds__(512, 1)
gemm2_f16(const __half* __restrict__ X,  const __half* __restrict__ Wa,
          const __half* __restrict__ Wx, const float* __restrict__ ba,
          const float* __restrict__ bb)
{
    __shared__ float s_ba[BN], s_bb[BN];

    const int t    = threadIdx.x;
    const int lane = t & 31;
    const int warp = t >> 5;
    const int g    = lane >> 2;
    const int tid4 = lane & 3;
    const int wm   = warp >> 2;     // 0..3
    const int wn   = warp & 3;      // 0..3
    const int m0   = blockIdx.y * BM;
    const int n0   = blockIdx.x * BN;

    uint32_t dyn_u32 = (uint32_t)__cvta_generic_to_shared(smem_raw);

    if (t < BN) { s_ba[t] = ba[n0 + t]; s_bb[t] = bb[n0 + t]; }

    float accA[2][4][4];
    float accW[2][4][4];
#pragma unroll
    for (int mi = 0; mi < 2; mi++)
#pragma unroll
        for (int ni = 0; ni < 4; ni++)
#pragma unroll
            for (int r = 0; r < 4; r++) { accA[mi][ni][r] = 0.f; accW[mi][ni][r] = 0.f; }

    // ---- per-lane ldmatrix base offsets (within a stage) ----
    uint32_t aBase[2];
#pragma unroll
    for (int mi = 0; mi < 2; mi++) {
        int row = wm * 32 + mi * 16 + (lane & 15);
        aBase[mi] = dyn_u32 + A_OFF + (uint32_t)(row * HST_B) + ((lane >> 4) << 4);
    }
    uint32_t bBaseA[2], bBaseW[2];
#pragma unroll
    for (int p = 0; p < 2; p++) {
        int row = wn * 32 + p * 16 + ((lane >> 4) << 3) + (lane & 7);
        uint32_t off = (uint32_t)(row * HST_B) + (((lane >> 3) & 1) << 4);
        bBaseA[p] = dyn_u32 + BA_OFF + off;
        bBaseW[p] = dyn_u32 + BW_OFF + off;
    }

    const __half* Xb  = X  + (size_t)m0 * MAX_K;
    const __half* Wab = Wa + (size_t)n0 * MAX_K;
    const __half* Wxb = Wx + (size_t)n0 * MAX_K;

    // staging: 1024 16B-chunks per matrix per K-chunk; 512 threads -> 2 each
    auto issue = [&](int ks, int b) {
        uint32_t dbase = dyn_u32 + (uint32_t)b * STG_BYTES;
        const size_t kof = (size_t)ks * 64;    // halves
#pragma unroll
        for (int i = 0; i < 2; i++) {
            int ch  = i * 512 + t;
            int row = ch >> 3, q = ch & 7;
            uint32_t so = (uint32_t)(row * HST_B + q * 16);
            size_t go = (size_t)row * MAX_K + kof + (size_t)q * 8;
            cp16(dbase + A_OFF  + so, Xb  + go);
            cp16(dbase + BA_OFF + so, Wab + go);
            cp16(dbase + BW_OFF + so, Wxb + go);
        }
        cp_commit();
    };

    issue(0, 0); issue(1, 1);

    for (int c = 0; c < NKS; c++) {
        const uint32_t stgofs = (uint32_t)(c % 3) * STG_BYTES;
        if (c < NKS - 1) cp_wait1(); else cp_wait0();
        __syncthreads();
        if (c + 2 < NKS) issue(c + 2, (c + 2) % 3);

#pragma unroll
        for (int kk = 0; kk < 4; kk++) {
            const uint32_t kb = stgofs + kk * 32;
            uint32_t af[2][4];
#pragma unroll
            for (int mi = 0; mi < 2; mi++) ldsm4(af[mi], aBase[mi] + kb);
            uint32_t bfA[2][4], bfW[2][4];
#pragma unroll
            for (int p = 0; p < 2; p++) {
                ldsm4(bfA[p], bBaseA[p] + kb);
                ldsm4(bfW[p], bBaseW[p] + kb);
            }
#pragma unroll
            for (int mi = 0; mi < 2; mi++)
#pragma unroll
                for (int ni = 0; ni < 4; ni++) {
                    const int p = ni >> 1, s = (ni & 1) * 2;
                    mma_f16(accA[mi][ni], af[mi], bfA[p][s], bfA[p][s + 1]);
                    mma_f16(accW[mi][ni], af[mi], bfW[p][s], bfW[p][s + 1]);
                }
        }
    }
    __syncthreads();

    // Epilogue: bias + fast sigmoid(alpha), interleaved float2 scratch
#pragma unroll
    for (int ni = 0; ni < 4; ni++) {
        const int col0 = n0 + wn * 32 + ni * 8 + 2 * tid4;
        const float ba0 = s_ba[col0 - n0], ba1 = s_ba[col0 - n0 + 1];
        const float bb0 = s_bb[col0 - n0], bb1 = s_bb[col0 - n0 + 1];
#pragma unroll
        for (int mi = 0; mi < 2; mi++) {
            const int row0 = m0 + wm * 32 + mi * 16 + g;
            {
                float4 v;
                v.x = fast_sigmoid(accA[mi][ni][0] + ba0);
                v.y = accW[mi][ni][0] + bb0;
                v.z = fast_sigmoid(accA[mi][ni][1] + ba1);
                v.w = accW[mi][ni][1] + bb1;
                *(float4*)&g_aw[(size_t)row0 * MAX_K + col0] = v;
            }
            {
                float4 v;
                v.x = fast_sigmoid(accA[mi][ni][2] + ba0);
                v.y = accW[mi][ni][2] + bb0;
                v.z = fast_sigmoid(accA[mi][ni][3] + ba1);
                v.w = accW[mi][ni][3] + bb1;
                *(float4*)&g_aw[(size_t)(row0 + 8) * MAX_K + col0] = v;
            }
        }
    }
}

// ---------------------------------------------------------------------------
// 3) Recurrence: tanh.approx, h only, 32-step prefetch groups (dist ~900 cyc)
// ---------------------------------------------------------------------------
__global__ void __launch_bounds__(64)
recur_kernel(const float* __restrict__ h0,
             float* __restrict__ hout,  // [T+1, BD]
             int T, int BD)
{
    const int idx = blockIdx.x * blockDim.x + threadIdx.x;
    if (idx >= BD) return;

    float h = h0[idx];
    hout[idx] = h;

    const float2* __restrict__ aw = g_aw + idx;
    float* __restrict__ hw = hout + BD + idx;

    float2 buf0[32], buf1[32];
#pragma unroll
    for (int u = 0; u < 32; u++) buf0[u] = aw[(size_t)u * BD];

    for (int tt = 0; tt < T; tt += 64) {
#pragma unroll
        for (int u = 0; u < 32; u++) buf1[u] = aw[(size_t)(tt + 32 + u) * BD];
#pragma unroll
        for (int u = 0; u < 32; u++) {
            const float a = buf0[u].x, w = buf0[u].y;
            float v = tanhx(h + w);
            h = fmaf(a, h - v, v);
            hw[(size_t)(tt + u) * BD] = h;
        }
        if (tt + 64 < T) {
#pragma unroll
            for (int u = 0; u < 32; u++) buf0[u] = aw[(size_t)(tt + 64 + u) * BD];
        }
#pragma unroll
        for (int u = 0; u < 32; u++) {
            const float a = buf1[u].x, w = buf1[u].y;
            float v = tanhx(h + w);
            h = fmaf(a, h - v, v);
            hw[(size_t)(tt + 32 + u) * BD] = h;
        }
    }
}

// ---------------------------------------------------------------------------
// 4) out = h^2 * sigmoid(h)
// ---------------------------------------------------------------------------
__global__ void __launch_bounds__(256)
out_kernel(const float* __restrict__ hsrc, float* __restrict__ out, int n4)
{
    int i = blockIdx.x * blockDim.x + threadIdx.x;
    if (i >= n4) return;
    float4 v = ((const float4*)hsrc)[i];
    float4 o;
    o.x = v.x * v.x * fast_sigmoid(v.x);
    o.y = v.y * v.y * fast_sigmoid(v.y);
    o.z = v.z * v.z * fast_sigmoid(v.z);
    o.w = v.w * v.w * fast_sigmoid(v.w);
    ((float4*)out)[i] = o;
}

// ---------------------------------------------------------------------------
extern "C" void kernel_launch(void* const* d_in, const int* in_sizes, int n_in,
                              void* d_out, int out_size)
{
    const float* x  = (const float*)d_in[0];
    const float* h0 = (const float*)d_in[1];
    const float* Wa = (const float*)d_in[2];
    const float* ba = (const float*)d_in[3];
    const float* Wx = (const float*)d_in[4];
    const float* bb = (const float*)d_in[5];

    const int BD = in_sizes[1];               // 8192
    const int D  = in_sizes[3];               // 1024
    const int M  = in_sizes[0] / D;           // 16384
    const int T  = in_sizes[0] / BD;          // 2048

    float* out  = (float*)d_out;
    float* hout = (float*)d_out + (size_t)T * BD;

    __half* gx;  cudaGetSymbolAddress((void**)&gx,  g_x);
    __half* gwa; cudaGetSymbolAddress((void**)&gwa, g_wa);
    __half* gwx; cudaGetSymbolAddress((void**)&gwx, g_wx);

    // 1) fp16 prepass
    {
        int nx4 = (M * D) / 4;
        int nw4 = (D * D) / 4;
        f2h_kernel<<<(nx4 + 255) / 256, 256>>>(x,  gx,  nx4);
        f2h_kernel<<<(nw4 + 255) / 256, 256>>>(Wa, gwa, nw4);
        f2h_kernel<<<(nw4 + 255) / 256, 256>>>(Wx, gwx, nw4);
    }

    // 2) dual fp16 GEMM
    const int SMEM_BYTES = 3 * STG_BYTES;           // 165888
    cudaFuncSetAttribute(gemm2_f16, cudaFuncAttributeMaxDynamicSharedMemorySize, SMEM_BYTES);
    dim3 grid(D / BN, M / BM);   // (8, 128) = 1024 CTAs
    gemm2_f16<<<grid, 512, SMEM_BYTES>>>(gx, gwa, gwx, ba, bb);

    // 3) recurrence (h only)
    recur_kernel<<<(BD + 63) / 64, 64>>>(h0, hout, T, BD);

    // 4) out = h * silu(h)
    int no4 = (T * BD) / 4;
    out_kernel<<<(no4 + 255) / 256, 256>>>(hout + BD, out, no4);
}

// round 9
// speedup vs baseline: 1.2118x; 1.0449x over previous
#include <cuda_runtime.h>
#include <cuda_fp16.h>
#include <math.h>
#include <stdint.h>

// ---------------------------------------------------------------------------
// E64AdditiveHCell — fp16 mma.sync + ldmatrix, BK=64, 2-CTA/SM edition
//  1) prepass: convert X, Wa, Wx to fp16 (rn)
//  2) dual fp16 tensor-core GEMM (m16n8k16, fp32 accum), 3-stage cp.async,
//     BM=128 BN=64, 256 threads, 2 CTAs/SM (barrier bubbles overlap):
//     alpha = sigmoid(X Wa^T + ba), wx = X Wx^T + b  -> interleaved float2
//  3) recurrence over T (tanh.approx, h only, 32-step prefetch groups)
//  4) out = h^2 * sigmoid(h)
// ---------------------------------------------------------------------------

#define BM 128
#define BN 64
#define NKS 16                 // K chunks: 1024 / 64
#define HST_B 144              // smem row stride in bytes (64 halves + 16B pad)
#define A_BYTES (128 * HST_B)  // 18432
#define B_BYTES (64 * HST_B)   // 9216
#define STG_BYTES (A_BYTES + 2 * B_BYTES)   // 36864
#define A_OFF  0
#define BA_OFF A_BYTES
#define BW_OFF (A_BYTES + B_BYTES)

#define MAX_T 2048
#define MAX_BD 8192
#define MAX_M 16384
#define MAX_K 1024
__device__ float2 g_aw[(size_t)MAX_T * MAX_BD];     // {alpha, wx}
__device__ __half g_x [(size_t)MAX_M * MAX_K];
__device__ __half g_wa[(size_t)MAX_K * MAX_K];
__device__ __half g_wx[(size_t)MAX_K * MAX_K];

// ---------------- helpers ----------------
__device__ __forceinline__ float ex2f(float x) {
    float r; asm("ex2.approx.ftz.f32 %0, %1;" : "=f"(r) : "f"(x)); return r;
}
__device__ __forceinline__ float rcpf(float x) {
    float r; asm("rcp.approx.ftz.f32 %0, %1;" : "=f"(r) : "f"(x)); return r;
}
__device__ __forceinline__ float tanhx(float x) {
    float r; asm("tanh.approx.f32 %0, %1;" : "=f"(r) : "f"(x)); return r;
}
__device__ __forceinline__ float fast_sigmoid(float x) {
    return rcpf(1.0f + ex2f(-1.4426950408889634f * x));
}
__device__ __forceinline__ void mma_f16(float c[4], const uint32_t a[4],
                                        uint32_t b0, uint32_t b1) {
    asm volatile(
        "mma.sync.aligned.m16n8k16.row.col.f32.f16.f16.f32 "
        "{%0,%1,%2,%3},{%4,%5,%6,%7},{%8,%9},{%0,%1,%2,%3};"
        : "+f"(c[0]), "+f"(c[1]), "+f"(c[2]), "+f"(c[3])
        : "r"(a[0]), "r"(a[1]), "r"(a[2]), "r"(a[3]), "r"(b0), "r"(b1));
}
__device__ __forceinline__ void ldsm4(uint32_t r[4], uint32_t addr) {
    asm volatile("ldmatrix.sync.aligned.m8n8.x4.shared.b16 {%0,%1,%2,%3}, [%4];"
        : "=r"(r[0]), "=r"(r[1]), "=r"(r[2]), "=r"(r[3]) : "r"(addr));
}
__device__ __forceinline__ void cp16(uint32_t dst, const void* src) {
    asm volatile("cp.async.cg.shared.global [%0], [%1], 16;" :: "r"(dst), "l"(src));
}
__device__ __forceinline__ void cp_commit() { asm volatile("cp.async.commit_group;"); }
__device__ __forceinline__ void cp_wait0()  { asm volatile("cp.async.wait_group 0;" ::: "memory"); }
__device__ __forceinline__ void cp_wait1()  { asm volatile("cp.async.wait_group 1;" ::: "memory"); }

// ---------------------------------------------------------------------------
// 1) fp32 -> fp16 prepass
// ---------------------------------------------------------------------------
__global__ void __launch_bounds__(256)
f2h_kernel(const float* __restrict__ src, __half* __restrict__ dst, int n4)
{
    int i = blockIdx.x * blockDim.x + threadIdx.x;
    if (i >= n4) return;
    float4 v = ((const float4*)src)[i];
    __half2 h0 = __floats2half2_rn(v.x, v.y);
    __half2 h1 = __floats2half2_rn(v.z, v.w);
    uint2 o;
    o.x = *(uint32_t*)&h0;
    o.y = *(uint32_t*)&h1;
    ((uint2*)dst)[i] = o;
}

// ---------------------------------------------------------------------------
// 2) fused dual fp16 GEMM: 256 threads, warps 4(m) x 2(n), warp tile 32x32/W,
//    2 CTAs per SM.
// ---------------------------------------------------------------------------
extern __shared__ __align__(128) char smem_raw[];

__global__ void __launch_bounds__(256, 2)
gemm2_f16(const __half* __restrict__ X,  const __half* __restrict__ Wa,
          const __half* __restrict__ Wx, const float* __restrict__ ba,
          const float* __restrict__ bb)
{
    __shared__ float s_ba[BN], s_bb[BN];

    const int t    = threadIdx.x;
    const int lane = t & 31;
    const int warp = t >> 5;
    const int g    = lane >> 2;
    const int tid4 = lane & 3;
    const int wm   = warp >> 1;     // 0..3
    const int wn   = warp & 1;      // 0..1
    const int m0   = blockIdx.y * BM;
    const int n0   = blockIdx.x * BN;

    uint32_t dyn_u32 = (uint32_t)__cvta_generic_to_shared(smem_raw);

    if (t < BN) { s_ba[t] = ba[n0 + t]; s_bb[t] = bb[n0 + t]; }

    float accA[2][4][4];
    float accW[2][4][4];
#pragma unroll
    for (int mi = 0; mi < 2; mi++)
#pragma unroll
        for (int ni = 0; ni < 4; ni++)
#pragma unroll
            for (int r = 0; r < 4; r++) { accA[mi][ni][r] = 0.f; accW[mi][ni][r] = 0.f; }

    // ---- per-lane ldmatrix base offsets (within a stage) ----
    uint32_t aBase[2];
#pragma unroll
    for (int mi = 0; mi < 2; mi++) {
        int row = wm * 32 + mi * 16 + (lane & 15);
        aBase[mi] = dyn_u32 + A_OFF + (uint32_t)(row * HST_B) + ((lane >> 4) << 4);
    }
    uint32_t bBaseA[2], bBaseW[2];
#pragma unroll
    for (int p = 0; p < 2; p++) {
        int row = wn * 32 + p * 16 + ((lane >> 4) << 3) + (lane & 7);
        uint32_t off = (uint32_t)(row * HST_B) + (((lane >> 3) & 1) << 4);
        bBaseA[p] = dyn_u32 + BA_OFF + off;
        bBaseW[p] = dyn_u32 + BW_OFF + off;
    }

    const __half* Xb  = X  + (size_t)m0 * MAX_K;
    const __half* Wab = Wa + (size_t)n0 * MAX_K;
    const __half* Wxb = Wx + (size_t)n0 * MAX_K;

    // staging per K-chunk: A 1024 16B-chunks, B 512 each; 256 threads
    auto issue = [&](int ks, int b) {
        uint32_t dbase = dyn_u32 + (uint32_t)b * STG_BYTES;
        const size_t kof = (size_t)ks * 64;    // halves
#pragma unroll
        for (int i = 0; i < 4; i++) {          // A
            int ch  = i * 256 + t;
            int row = ch >> 3, q = ch & 7;
            uint32_t so = (uint32_t)(row * HST_B + q * 16);
            cp16(dbase + A_OFF + so, Xb + (size_t)row * MAX_K + kof + (size_t)q * 8);
        }
#pragma unroll
        for (int i = 0; i < 2; i++) {          // B_A and B_W
            int ch  = i * 256 + t;
            int row = ch >> 3, q = ch & 7;
            uint32_t so = (uint32_t)(row * HST_B + q * 16);
            size_t go = (size_t)row * MAX_K + kof + (size_t)q * 8;
            cp16(dbase + BA_OFF + so, Wab + go);
            cp16(dbase + BW_OFF + so, Wxb + go);
        }
        cp_commit();
    };

    issue(0, 0); issue(1, 1);

    for (int c = 0; c < NKS; c++) {
        const uint32_t stgofs = (uint32_t)(c % 3) * STG_BYTES;
        if (c < NKS - 1) cp_wait1(); else cp_wait0();
        __syncthreads();
        if (c + 2 < NKS) issue(c + 2, (c + 2) % 3);

#pragma unroll
        for (int kk = 0; kk < 4; kk++) {
            const uint32_t kb = stgofs + kk * 32;
            uint32_t af[2][4];
#pragma unroll
            for (int mi = 0; mi < 2; mi++) ldsm4(af[mi], aBase[mi] + kb);
            uint32_t bfA[2][4], bfW[2][4];
#pragma unroll
            for (int p = 0; p < 2; p++) {
                ldsm4(bfA[p], bBaseA[p] + kb);
                ldsm4(bfW[p], bBaseW[p] + kb);
            }
#pragma unroll
            for (int mi = 0; mi < 2; mi++)
#pragma unroll
                for (int ni = 0; ni < 4; ni++) {
                    const int p = ni >> 1, s = (ni & 1) * 2;
                    mma_f16(accA[mi][ni], af[mi], bfA[p][s], bfA[p][s + 1]);
                    mma_f16(accW[mi][ni], af[mi], bfW[p][s], bfW[p][s + 1]);
                }
        }
    }
    __syncthreads();

    // Epilogue: bias + fast sigmoid(alpha), interleaved float2 scratch
#pragma unroll
    for (int ni = 0; ni < 4; ni++) {
        const int col0 = n0 + wn * 32 + ni * 8 + 2 * tid4;
        const float ba0 = s_ba[col0 - n0], ba1 = s_ba[col0 - n0 + 1];
        const float bb0 = s_bb[col0 - n0], bb1 = s_bb[col0 - n0 + 1];
#pragma unroll
        for (int mi = 0; mi < 2; mi++) {
            const int row0 = m0 + wm * 32 + mi * 16 + g;
            {
                float4 v;
                v.x = fast_sigmoid(accA[mi][ni][0] + ba0);
                v.y = accW[mi][ni][0] + bb0;
                v.z = fast_sigmoid(accA[mi][ni][1] + ba1);
                v.w = accW[mi][ni][1] + bb1;
                *(float4*)&g_aw[(size_t)row0 * MAX_K + col0] = v;
            }
            {
                float4 v;
                v.x = fast_sigmoid(accA[mi][ni][2] + ba0);
                v.y = accW[mi][ni][2] + bb0;
                v.z = fast_sigmoid(accA[mi][ni][3] + ba1);
                v.w = accW[mi][ni][3] + bb1;
                *(float4*)&g_aw[(size_t)(row0 + 8) * MAX_K + col0] = v;
            }
        }
    }
}

// ---------------------------------------------------------------------------
// 3) Recurrence: tanh.approx, h only, 32-step prefetch groups
// ---------------------------------------------------------------------------
__global__ void __launch_bounds__(64)
recur_kernel(const float* __restrict__ h0,
             float* __restrict__ hout,  // [T+1, BD]
             int T, int BD)
{
    const int idx = blockIdx.x * blockDim.x + threadIdx.x;
    if (idx >= BD) return;

    float h = h0[idx];
    hout[idx] = h;

    const float2* __restrict__ aw = g_aw + idx;
    float* __restrict__ hw = hout + BD + idx;

    float2 buf0[32], buf1[32];
#pragma unroll
    for (int u = 0; u < 32; u++) buf0[u] = aw[(size_t)u * BD];

    for (int tt = 0; tt < T; tt += 64) {
#pragma unroll
        for (int u = 0; u < 32; u++) buf1[u] = aw[(size_t)(tt + 32 + u) * BD];
#pragma unroll
        for (int u = 0; u < 32; u++) {
            const float a = buf0[u].x, w = buf0[u].y;
            float v = tanhx(h + w);
            h = fmaf(a, h - v, v);
            hw[(size_t)(tt + u) * BD] = h;
        }
        if (tt + 64 < T) {
#pragma unroll
            for (int u = 0; u < 32; u++) buf0[u] = aw[(size_t)(tt + 64 + u) * BD];
        }
#pragma unroll
        for (int u = 0; u < 32; u++) {
            const float a = buf1[u].x, w = buf1[u].y;
            float v = tanhx(h + w);
            h = fmaf(a, h - v, v);
            hw[(size_t)(tt + 32 + u) * BD] = h;
        }
    }
}

// ---------------------------------------------------------------------------
// 4) out = h^2 * sigmoid(h)
// ---------------------------------------------------------------------------
__global__ void __launch_bounds__(256)
out_kernel(const float* __restrict__ hsrc, float* __restrict__ out, int n4)
{
    int i = blockIdx.x * blockDim.x + threadIdx.x;
    if (i >= n4) return;
    float4 v = ((const float4*)hsrc)[i];
    float4 o;
    o.x = v.x * v.x * fast_sigmoid(v.x);
    o.y = v.y * v.y * fast_sigmoid(v.y);
    o.z = v.z * v.z * fast_sigmoid(v.z);
    o.w = v.w * v.w * fast_sigmoid(v.w);
    ((float4*)out)[i] = o;
}

// ---------------------------------------------------------------------------
extern "C" void kernel_launch(void* const* d_in, const int* in_sizes, int n_in,
                              void* d_out, int out_size)
{
    const float* x  = (const float*)d_in[0];
    const float* h0 = (const float*)d_in[1];
    const float* Wa = (const float*)d_in[2];
    const float* ba = (const float*)d_in[3];
    const float* Wx = (const float*)d_in[4];
    const float* bb = (const float*)d_in[5];

    const int BD = in_sizes[1];               // 8192
    const int D  = in_sizes[3];               // 1024
    const int M  = in_sizes[0] / D;           // 16384
    const int T  = in_sizes[0] / BD;          // 2048

    float* out  = (float*)d_out;
    float* hout = (float*)d_out + (size_t)T * BD;

    __half* gx;  cudaGetSymbolAddress((void**)&gx,  g_x);
    __half* gwa; cudaGetSymbolAddress((void**)&gwa, g_wa);
    __half* gwx; cudaGetSymbolAddress((void**)&gwx, g_wx);

    // 1) fp16 prepass
    {
        int nx4 = (M * D) / 4;
        int nw4 = (D * D) / 4;
        f2h_kernel<<<(nx4 + 255) / 256, 256>>>(x,  gx,  nx4);
        f2h_kernel<<<(nw4 + 255) / 256, 256>>>(Wa, gwa, nw4);
        f2h_kernel<<<(nw4 + 255) / 256, 256>>>(Wx, gwx, nw4);
    }

    // 2) dual fp16 GEMM, 2 CTAs/SM
    const int SMEM_BYTES = 3 * STG_BYTES;           // 110592
    cudaFuncSetAttribute(gemm2_f16, cudaFuncAttributeMaxDynamicSharedMemorySize, SMEM_BYTES);
    dim3 grid(D / BN, M / BM);   // (16, 128) = 2048 CTAs
    gemm2_f16<<<grid, 256, SMEM_BYTES>>>(gx, gwa, gwx, ba, bb);

    // 3) recurrence (h only)
    recur_kernel<<<(BD + 63) / 64, 64>>>(h0, hout, T, BD);

    // 4) out = h * silu(h)
    int no4 = (T * BD) / 4;
    out_kernel<<<(no4 + 255) / 256, 256>>>(hout + BD, out, no4);
}

// round 10
// speedup vs baseline: 1.4674x; 1.2109x over previous
#include <cuda_runtime.h>
#include <cuda_fp16.h>
#include <math.h>
#include <stdint.h>

// ---------------------------------------------------------------------------
// E64AdditiveHCell — fp16 mma.sync + ldmatrix, fp16 scratch edition
//  1) prepass: convert X, Wa, Wx to fp16 (rn)
//  2) dual fp16 tensor-core GEMM (m16n8k16, fp32 accum), 3-stage cp.async,
//     BM=128 BN=64, 256 threads, 2 CTAs/SM:
//     alpha = sigmoid(X Wa^T + ba), wx = X Wx^T + b  -> half2 {alpha, wx}
//  3) recurrence over T (tanh.approx) with fused out = h^2 * sigmoid(h)
// ---------------------------------------------------------------------------

#define BM 128
#define BN 64
#define NKS 16                 // K chunks: 1024 / 64
#define HST_B 144              // smem row stride in bytes (64 halves + 16B pad)
#define A_BYTES (128 * HST_B)  // 18432
#define B_BYTES (64 * HST_B)   // 9216
#define STG_BYTES (A_BYTES + 2 * B_BYTES)   // 36864
#define A_OFF  0
#define BA_OFF A_BYTES
#define BW_OFF (A_BYTES + B_BYTES)

#define MAX_T 2048
#define MAX_BD 8192
#define MAX_M 16384
#define MAX_K 1024
__device__ __half2 g_aw[(size_t)MAX_T * MAX_BD];    // {alpha, wx} fp16
__device__ __half  g_x [(size_t)MAX_M * MAX_K];
__device__ __half  g_wa[(size_t)MAX_K * MAX_K];
__device__ __half  g_wx[(size_t)MAX_K * MAX_K];

// ---------------- helpers ----------------
__device__ __forceinline__ float ex2f(float x) {
    float r; asm("ex2.approx.ftz.f32 %0, %1;" : "=f"(r) : "f"(x)); return r;
}
__device__ __forceinline__ float rcpf(float x) {
    float r; asm("rcp.approx.ftz.f32 %0, %1;" : "=f"(r) : "f"(x)); return r;
}
__device__ __forceinline__ float tanhx(float x) {
    float r; asm("tanh.approx.f32 %0, %1;" : "=f"(r) : "f"(x)); return r;
}
__device__ __forceinline__ float fast_sigmoid(float x) {
    return rcpf(1.0f + ex2f(-1.4426950408889634f * x));
}
__device__ __forceinline__ void mma_f16(float c[4], const uint32_t a[4],
                                        uint32_t b0, uint32_t b1) {
    asm volatile(
        "mma.sync.aligned.m16n8k16.row.col.f32.f16.f16.f32 "
        "{%0,%1,%2,%3},{%4,%5,%6,%7},{%8,%9},{%0,%1,%2,%3};"
        : "+f"(c[0]), "+f"(c[1]), "+f"(c[2]), "+f"(c[3])
        : "r"(a[0]), "r"(a[1]), "r"(a[2]), "r"(a[3]), "r"(b0), "r"(b1));
}
__device__ __forceinline__ void ldsm4(uint32_t r[4], uint32_t addr) {
    asm volatile("ldmatrix.sync.aligned.m8n8.x4.shared.b16 {%0,%1,%2,%3}, [%4];"
        : "=r"(r[0]), "=r"(r[1]), "=r"(r[2]), "=r"(r[3]) : "r"(addr));
}
__device__ __forceinline__ void cp16(uint32_t dst, const void* src) {
    asm volatile("cp.async.cg.shared.global [%0], [%1], 16;" :: "r"(dst), "l"(src));
}
__device__ __forceinline__ void cp_commit() { asm volatile("cp.async.commit_group;"); }
__device__ __forceinline__ void cp_wait0()  { asm volatile("cp.async.wait_group 0;" ::: "memory"); }
__device__ __forceinline__ void cp_wait1()  { asm volatile("cp.async.wait_group 1;" ::: "memory"); }

// ---------------------------------------------------------------------------
// 1) fp32 -> fp16 prepass
// ---------------------------------------------------------------------------
__global__ void __launch_bounds__(256)
f2h_kernel(const float* __restrict__ src, __half* __restrict__ dst, int n4)
{
    int i = blockIdx.x * blockDim.x + threadIdx.x;
    if (i >= n4) return;
    float4 v = ((const float4*)src)[i];
    __half2 h0 = __floats2half2_rn(v.x, v.y);
    __half2 h1 = __floats2half2_rn(v.z, v.w);
    uint2 o;
    o.x = *(uint32_t*)&h0;
    o.y = *(uint32_t*)&h1;
    ((uint2*)dst)[i] = o;
}

// ---------------------------------------------------------------------------
// 2) fused dual fp16 GEMM: 256 threads, warps 4(m) x 2(n), warp tile 32x32/W,
//    2 CTAs per SM. Epilogue stores half2 {alpha, wx}.
// ---------------------------------------------------------------------------
extern __shared__ __align__(128) char smem_raw[];

__global__ void __launch_bounds__(256, 2)
gemm2_f16(const __half* __restrict__ X,  const __half* __restrict__ Wa,
          const __half* __restrict__ Wx, const float* __restrict__ ba,
          const float* __restrict__ bb)
{
    __shared__ float s_ba[BN], s_bb[BN];

    const int t    = threadIdx.x;
    const int lane = t & 31;
    const int warp = t >> 5;
    const int g    = lane >> 2;
    const int tid4 = lane & 3;
    const int wm   = warp >> 1;     // 0..3
    const int wn   = warp & 1;      // 0..1
    const int m0   = blockIdx.y * BM;
    const int n0   = blockIdx.x * BN;

    uint32_t dyn_u32 = (uint32_t)__cvta_generic_to_shared(smem_raw);

    if (t < BN) { s_ba[t] = ba[n0 + t]; s_bb[t] = bb[n0 + t]; }

    float accA[2][4][4];
    float accW[2][4][4];
#pragma unroll
    for (int mi = 0; mi < 2; mi++)
#pragma unroll
        for (int ni = 0; ni < 4; ni++)
#pragma unroll
            for (int r = 0; r < 4; r++) { accA[mi][ni][r] = 0.f; accW[mi][ni][r] = 0.f; }

    // ---- per-lane ldmatrix base offsets (within a stage) ----
    uint32_t aBase[2];
#pragma unroll
    for (int mi = 0; mi < 2; mi++) {
        int row = wm * 32 + mi * 16 + (lane & 15);
        aBase[mi] = dyn_u32 + A_OFF + (uint32_t)(row * HST_B) + ((lane >> 4) << 4);
    }
    uint32_t bBaseA[2], bBaseW[2];
#pragma unroll
    for (int p = 0; p < 2; p++) {
        int row = wn * 32 + p * 16 + ((lane >> 4) << 3) + (lane & 7);
        uint32_t off = (uint32_t)(row * HST_B) + (((lane >> 3) & 1) << 4);
        bBaseA[p] = dyn_u32 + BA_OFF + off;
        bBaseW[p] = dyn_u32 + BW_OFF + off;
    }

    const __half* Xb  = X  + (size_t)m0 * MAX_K;
    const __half* Wab = Wa + (size_t)n0 * MAX_K;
    const __half* Wxb = Wx + (size_t)n0 * MAX_K;

    auto issue = [&](int ks, int b) {
        uint32_t dbase = dyn_u32 + (uint32_t)b * STG_BYTES;
        const size_t kof = (size_t)ks * 64;    // halves
#pragma unroll
        for (int i = 0; i < 4; i++) {          // A: 1024 16B-chunks
            int ch  = i * 256 + t;
            int row = ch >> 3, q = ch & 7;
            uint32_t so = (uint32_t)(row * HST_B + q * 16);
            cp16(dbase + A_OFF + so, Xb + (size_t)row * MAX_K + kof + (size_t)q * 8);
        }
#pragma unroll
        for (int i = 0; i < 2; i++) {          // B_A and B_W: 512 each
            int ch  = i * 256 + t;
            int row = ch >> 3, q = ch & 7;
            uint32_t so = (uint32_t)(row * HST_B + q * 16);
            size_t go = (size_t)row * MAX_K + kof + (size_t)q * 8;
            cp16(dbase + BA_OFF + so, Wab + go);
            cp16(dbase + BW_OFF + so, Wxb + go);
        }
        cp_commit();
    };

    issue(0, 0); issue(1, 1);

    for (int c = 0; c < NKS; c++) {
        const uint32_t stgofs = (uint32_t)(c % 3) * STG_BYTES;
        if (c < NKS - 1) cp_wait1(); else cp_wait0();
        __syncthreads();
        if (c + 2 < NKS) issue(c + 2, (c + 2) % 3);

#pragma unroll
        for (int kk = 0; kk < 4; kk++) {
            const uint32_t kb = stgofs + kk * 32;
            uint32_t af[2][4];
#pragma unroll
            for (int mi = 0; mi < 2; mi++) ldsm4(af[mi], aBase[mi] + kb);
            uint32_t bfA[2][4], bfW[2][4];
#pragma unroll
            for (int p = 0; p < 2; p++) {
                ldsm4(bfA[p], bBaseA[p] + kb);
                ldsm4(bfW[p], bBaseW[p] + kb);
            }
#pragma unroll
            for (int mi = 0; mi < 2; mi++)
#pragma unroll
                for (int ni = 0; ni < 4; ni++) {
                    const int p = ni >> 1, s = (ni & 1) * 2;
                    mma_f16(accA[mi][ni], af[mi], bfA[p][s], bfA[p][s + 1]);
                    mma_f16(accW[mi][ni], af[mi], bfW[p][s], bfW[p][s + 1]);
                }
        }
    }
    __syncthreads();

    // Epilogue: bias + fast sigmoid(alpha), half2 {alpha, wx} stores (8B/pair)
#pragma unroll
    for (int ni = 0; ni < 4; ni++) {
        const int col0 = n0 + wn * 32 + ni * 8 + 2 * tid4;
        const float ba0 = s_ba[col0 - n0], ba1 = s_ba[col0 - n0 + 1];
        const float bb0 = s_bb[col0 - n0], bb1 = s_bb[col0 - n0 + 1];
#pragma unroll
        for (int mi = 0; mi < 2; mi++) {
            const int row0 = m0 + wm * 32 + mi * 16 + g;
            {
                __half2 p0 = __floats2half2_rn(
                    fast_sigmoid(accA[mi][ni][0] + ba0), accW[mi][ni][0] + bb0);
                __half2 p1 = __floats2half2_rn(
                    fast_sigmoid(accA[mi][ni][1] + ba1), accW[mi][ni][1] + bb1);
                uint2 v = { *(uint32_t*)&p0, *(uint32_t*)&p1 };
                *(uint2*)&g_aw[(size_t)row0 * MAX_K + col0] = v;
            }
            {
                __half2 p0 = __floats2half2_rn(
                    fast_sigmoid(accA[mi][ni][2] + ba0), accW[mi][ni][2] + bb0);
                __half2 p1 = __floats2half2_rn(
                    fast_sigmoid(accA[mi][ni][3] + ba1), accW[mi][ni][3] + bb1);
                uint2 v = { *(uint32_t*)&p0, *(uint32_t*)&p1 };
                *(uint2*)&g_aw[(size_t)(row0 + 8) * MAX_K + col0] = v;
            }
        }
    }
}

// ---------------------------------------------------------------------------
// 3) Recurrence + fused out: tanh.approx chain (~28 cyc), silu off-path.
//    Reads half2 {alpha, wx} (4B/step), 32-step prefetch groups.
// ---------------------------------------------------------------------------
__global__ void __launch_bounds__(64)
recur_kernel(const float* __restrict__ h0,
             float* __restrict__ out,   // [T, BD]
             float* __restrict__ hout,  // [T+1, BD]
             int T, int BD)
{
    const int idx = blockIdx.x * blockDim.x + threadIdx.x;
    if (idx >= BD) return;

    float h = h0[idx];
    hout[idx] = h;

    const __half2* __restrict__ aw = g_aw + idx;
    float* __restrict__ hw = hout + BD + idx;
    float* __restrict__ ow = out + idx;

    uint32_t buf0[32], buf1[32];
#pragma unroll
    for (int u = 0; u < 32; u++) buf0[u] = *(const uint32_t*)&aw[(size_t)u * BD];

    for (int tt = 0; tt < T; tt += 64) {
#pragma unroll
        for (int u = 0; u < 32; u++)
            buf1[u] = *(const uint32_t*)&aw[(size_t)(tt + 32 + u) * BD];
#pragma unroll
        for (int u = 0; u < 32; u++) {
            float2 f = __half22float2(*(__half2*)&buf0[u]);
            const float a = f.x, w = f.y;
            float v = tanhx(h + w);
            h = fmaf(a, h - v, v);
            float sg = fast_sigmoid(h);
            size_t o = (size_t)(tt + u) * BD;
            ow[o] = h * h * sg;
            hw[o] = h;
        }
        if (tt + 64 < T) {
#pragma unroll
            for (int u = 0; u < 32; u++)
                buf0[u] = *(const uint32_t*)&aw[(size_t)(tt + 64 + u) * BD];
        }
#pragma unroll
        for (int u = 0; u < 32; u++) {
            float2 f = __half22float2(*(__half2*)&buf1[u]);
            const float a = f.x, w = f.y;
            float v = tanhx(h + w);
            h = fmaf(a, h - v, v);
            float sg = fast_sigmoid(h);
            size_t o = (size_t)(tt + 32 + u) * BD;
            ow[o] = h * h * sg;
            hw[o] = h;
        }
    }
}

// ---------------------------------------------------------------------------
extern "C" void kernel_launch(void* const* d_in, const int* in_sizes, int n_in,
                              void* d_out, int out_size)
{
    const float* x  = (const float*)d_in[0];
    const float* h0 = (const float*)d_in[1];
    const float* Wa = (const float*)d_in[2];
    const float* ba = (const float*)d_in[3];
    const float* Wx = (const float*)d_in[4];
    const float* bb = (const float*)d_in[5];

    const int BD = in_sizes[1];               // 8192
    const int D  = in_sizes[3];               // 1024
    const int M  = in_sizes[0] / D;           // 16384
    const int T  = in_sizes[0] / BD;          // 2048

    float* out  = (float*)d_out;
    float* hout = (float*)d_out + (size_t)T * BD;

    __half* gx;  cudaGetSymbolAddress((void**)&gx,  g_x);
    __half* gwa; cudaGetSymbolAddress((void**)&gwa, g_wa);
    __half* gwx; cudaGetSymbolAddress((void**)&gwx, g_wx);

    // 1) fp16 prepass
    {
        int nx4 = (M * D) / 4;
        int nw4 = (D * D) / 4;
        f2h_kernel<<<(nx4 + 255) / 256, 256>>>(x,  gx,  nx4);
        f2h_kernel<<<(nw4 + 255) / 256, 256>>>(Wa, gwa, nw4);
        f2h_kernel<<<(nw4 + 255) / 256, 256>>>(Wx, gwx, nw4);
    }

    // 2) dual fp16 GEMM, 2 CTAs/SM
    const int SMEM_BYTES = 3 * STG_BYTES;           // 110592
    cudaFuncSetAttribute(gemm2_f16, cudaFuncAttributeMaxDynamicSharedMemorySize, SMEM_BYTES);
    dim3 grid(D / BN, M / BM);   // (16, 128) = 2048 CTAs
    gemm2_f16<<<grid, 256, SMEM_BYTES>>>(gx, gwa, gwx, ba, bb);

    // 3) recurrence + fused out
    recur_kernel<<<(BD + 63) / 64, 64>>>(h0, out, hout, T, BD);
}